// round 8
// baseline (speedup 1.0000x reference)
#include <cuda_runtime.h>
#include <math.h>

// GEBLNet fused kernel, round 8 = round-5 base + two isolated changes:
//  (1) weights packed {ar,ai,er,ei} in ONE float4 LDG (was float2+float4)
//  (2) sC padded stride S+1 so stage_m reads v-pairs as LDS.128

#define U    12
#define S1   13
#define S2   25
#define NB1  6
#define NB2  12
#define T1   (U*S1)      // 156
#define T2   (U*S2)      // 300
#define PS1  (S1+1)      // 14
#define PS2  (S2+1)      // 26
#define NT   160
#define NPTF 180

typedef unsigned long long u64;

__device__ float4 g_AE1[NB1*T1];   // {ar, ai, er, ei}, task-major
__device__ float4 g_AE2[NB2*T2];
__device__ float2 g_C1[T1], g_C2[T2];

__device__ __forceinline__ u64 pk(float lo, float hi) {
    u64 r; asm("mov.b64 %0,{%1,%2};" : "=l"(r) : "f"(lo), "f"(hi)); return r;
}
__device__ __forceinline__ void fma2(u64& d, u64 a, u64 b) {
    asm("fma.rn.f32x2 %0,%1,%2,%0;" : "+l"(d) : "l"(a), "l"(b));
}
__device__ __forceinline__ float2 up(u64 a) {
    float2 f; asm("mov.b64 {%0,%1},%2;" : "=f"(f.x), "=f"(f.y) : "l"(a)); return f;
}

__global__ void prep_w(const float* __restrict__ w1, const float* __restrict__ w2)
{
    int t = blockIdx.x * blockDim.x + threadIdx.x;
    if (t < T1) {
        const float* b = w1 + (size_t)t * S1 * 2;
        for (int w = 0; w < NB1; w++)
            g_AE1[w*T1 + t] = make_float4(b[2*w], b[2*w + 1],
                                          b[2*(NB1+w)], b[2*(NB1+w) + 1]);
        g_C1[t] = make_float2(b[2*(2*NB1)], b[2*(2*NB1) + 1]);
    }
    if (t < T2) {
        const float* b = w2 + (size_t)t * S2 * 2;
        for (int w = 0; w < NB2; w++)
            g_AE2[w*T2 + t] = make_float4(b[2*w], b[2*w + 1],
                                          b[2*(NB2+w)], b[2*(NB2+w) + 1]);
        g_C2[t] = make_float2(b[2*(2*NB2)], b[2*(2*NB2) + 1]);
    }
}

// C[u,v] = sum_w a_w*W[w] + sum_w e_w*W[w]^H + c*I  (single accumulator):
//   acc[(i,k)] += {ar,ar}.b[(i,k)] + {ai,ai}.bs[(i,k)]
//              + {er,-er}.b[(k,i)] + {-ei,ei}.bs[(k,i)]
template<int S, int NB, int TPT, int PS>
__device__ __forceinline__ void stage_c(const float4* __restrict__ gAE,
                                        const float2* __restrict__ gC,
                                        const ulonglong2* __restrict__ sWp,
                                        u64* __restrict__ sC, int tid)
{
    const int T = U * S;
    const int H = T / TPT;
    if (tid < H) {
        u64 acc[TPT][9];
#pragma unroll
        for (int t = 0; t < TPT; t++)
#pragma unroll
            for (int e = 0; e < 9; e++) acc[t][e] = 0ull;

#pragma unroll
        for (int w = 0; w < NB; ++w) {
            ulonglong2 bp[9];
#pragma unroll
            for (int e = 0; e < 9; e++) bp[e] = sWp[w*9 + e];   // {b, bs}

#pragma unroll
            for (int t = 0; t < TPT; t++) {
                int task = tid + t * H;
                float4 f = __ldg(gAE + w*T + task);
                u64 ar = pk(f.x, f.x), ai = pk(f.y, f.y);
                u64 er = pk(f.z, -f.z), ei = pk(-f.w, f.w);
#pragma unroll
                for (int i = 0; i < 3; i++)
#pragma unroll
                    for (int k = 0; k < 3; k++) {
                        int e = i*3 + k, et = k*3 + i;
                        fma2(acc[t][e], ar, bp[e].x);
                        fma2(acc[t][e], ai, bp[e].y);
                        fma2(acc[t][e], er, bp[et].x);
                        fma2(acc[t][e], ei, bp[et].y);
                    }
            }
        }
        const u64 one2 = pk(1.0f, 1.0f);
#pragma unroll
        for (int t = 0; t < TPT; t++) {
            int task = tid + t * H;
            float2 cw = __ldg(gC + task);
            u64 cc = pk(cw.x, cw.y);
            fma2(acc[t][0], one2, cc);
            fma2(acc[t][4], one2, cc);
            fma2(acc[t][8], one2, cc);
            int uu = task / S, vv = task - uu * S;
            u64* dst = sC + uu * PS + vv;
#pragma unroll
            for (int e = 0; e < 9; e++) dst[e * (U*PS)] = acc[t][e];
        }
    }
}

// wout[u](i,k) = sum_{v<NB} W[v](i,:)C[u,v](:,k)
//             + sum_{v<NB} W[v]^H(i,:)C[u,NB+v](:,k) + C[u,2NB](i,k)
template<int S, int NB, int PS>
__device__ __forceinline__ void stage_m(const ulonglong2* __restrict__ sWp,
                                        const u64* __restrict__ sC,
                                        u64* __restrict__ sM, int tid)
{
    if (tid < U * 9) {
        int u = tid / 9, e = tid % 9;
        int i = e / 3, k = e % 3;
        u64 a1 = 0ull, a2 = 0ull, a2c = 0ull;
        const u64* base = sC + u * PS;
#pragma unroll
        for (int j = 0; j < 3; ++j) {
            const ulonglong2* r2 = reinterpret_cast<const ulonglong2*>(base + (j*3 + k)*(U*PS));
#pragma unroll
            for (int vp = 0; vp < NB/2; ++vp) {
                ulonglong2 c = r2[vp];
                float2 b0 = up(sWp[(2*vp  )*9 + i*3 + j].x);
                float2 b1 = up(sWp[(2*vp+1)*9 + i*3 + j].x);
                fma2(a1, pk(b0.x, b0.x), c.x);
                fma2(a2, pk(b0.y, b0.y), c.x);
                fma2(a1, pk(b1.x, b1.x), c.y);
                fma2(a2, pk(b1.y, b1.y), c.y);
            }
#pragma unroll
            for (int vp = 0; vp < NB/2; ++vp) {
                ulonglong2 c = r2[NB/2 + vp];
                float2 b0 = up(sWp[(2*vp  )*9 + j*3 + i].x);
                float2 b1 = up(sWp[(2*vp+1)*9 + j*3 + i].x);
                fma2(a1,  pk(b0.x, b0.x), c.x);
                fma2(a2c, pk(b0.y, b0.y), c.x);
                fma2(a1,  pk(b1.x, b1.x), c.y);
                fma2(a2c, pk(b1.y, b1.y), c.y);
            }
        }
        float2 p = up(a1), q = up(a2), qc = up(a2c);
        float2 ci = up(base[(i*3 + k)*(U*PS) + 2*NB]);
        sM[u*9 + e] = pk(p.x - q.y + qc.y + ci.x,
                         p.y + q.x - qc.x + ci.y);
    }
}

__global__ __launch_bounds__(NT, 4)
void gebl_kernel(const float* __restrict__ x,
                 const float* __restrict__ dw,
                 const float* __restrict__ db,
                 float* __restrict__ out)
{
    __shared__ __align__(16) ulonglong2 sWp[NB2 * 9];   // 1728 B
    __shared__ __align__(16) u64 sC[9 * U * PS2];       // 22464 B
    __shared__ u64   sM[U * 9];
    __shared__ float sTrRe[U], sTrIm[U], sAbs[U], sScale[U];
    __shared__ float sNormInv;

    const int tid   = threadIdx.x;
    const int point = blockIdx.x;
    const float2* xp = reinterpret_cast<const float2*>(x + (size_t)point * NPTF) + 4 * 9;

    // ---- Build base W1 ----
    if (tid < NB1 * 9) {
        float2 v = __ldg(xp + tid);
        sWp[tid] = make_ulonglong2(pk(v.x, v.y), pk(-v.y, v.x));
    }
    __syncthreads();

    // ---- Layer 1 ----
    stage_c<S1, NB1, 1, PS1>(g_AE1, g_C1, sWp, sC, tid);
    __syncthreads();
    stage_m<S1, NB1, PS1>(sWp, sC, sM, tid);
    __syncthreads();

    if (tid < U) {
        const u64* m = sM + tid*9;
        float2 t0 = up(m[0]), t4 = up(m[4]), t8 = up(m[8]);
        float trRe = t0.x + t4.x + t8.x;
        float trIm = t0.y + t4.y + t8.y;
        float t = fmaxf(trRe, 0.0f);
        sAbs[tid]   = t * sqrtf(trRe*trRe + trIm*trIm);
        sScale[tid] = t;
    }
    __syncthreads();
    if (tid == 0) {
        float s = 0.f;
#pragma unroll
        for (int u = 0; u < U; u++) s += sAbs[u];
        sNormInv = 1.0f / fmaxf(s * (1.0f / U), 0.001f);
    }
    __syncthreads();

    // ---- Build base W2 ----
    if (tid < U * 9) {
        int ch = tid / 9;
        float s = sScale[ch] * sNormInv;
        float2 m = up(sM[tid]);
        sWp[tid] = make_ulonglong2(pk(s*m.x, s*m.y), pk(-s*m.y, s*m.x));
    }
    __syncthreads();

    // ---- Layer 2 (2 tasks/thread) ----
    stage_c<S2, NB2, 2, PS2>(g_AE2, g_C2, sWp, sC, tid);
    __syncthreads();
    stage_m<S2, NB2, PS2>(sWp, sC, sM, tid);
    __syncthreads();

    // ---- Layer-2 scalars + head ----
    if (tid < U) {
        const u64* m = sM + tid*9;
        float2 t0 = up(m[0]), t4 = up(m[4]), t8 = up(m[8]);
        float trRe = t0.x + t4.x + t8.x;
        float trIm = t0.y + t4.y + t8.y;
        float t = fmaxf(trRe, 0.0f);
        sTrRe[tid]  = trRe;
        sTrIm[tid]  = trIm;
        sAbs[tid]   = t * sqrtf(trRe*trRe + trIm*trIm);
        sScale[tid] = t;
    }
    __syncthreads();
    if (tid == 0) {
        float s = 0.f;
#pragma unroll
        for (int u = 0; u < U; u++) s += sAbs[u];
        float inv_norm = 1.0f / fmaxf(s * (1.0f / U), 0.001f);
        float o = __ldg(&db[0]);
#pragma unroll
        for (int u = 0; u < U; u++) {
            float sc = sScale[u] * inv_norm * (1.0f / 3.0f);
            o = fmaf(sc * sTrRe[u], __ldg(&dw[2*u]),     o);
            o = fmaf(sc * sTrIm[u], __ldg(&dw[2*u + 1]), o);
        }
        out[point] = o;
    }
}

extern "C" void kernel_launch(void* const* d_in, const int* in_sizes, int n_in,
                              void* d_out, int out_size)
{
    const float* x  = (const float*)d_in[0];
    const float* w1 = (const float*)d_in[1];
    const float* w2 = (const float*)d_in[2];
    const float* dw = (const float*)d_in[3];
    const float* db = (const float*)d_in[4];
    float* out = (float*)d_out;

    int points = in_sizes[0] / NPTF;   // 8192

    prep_w<<<1, 320>>>(w1, w2);
    gebl_kernel<<<points, NT>>>(x, dw, db, out);
}

// round 9
// speedup vs baseline: 1.2223x; 1.2223x over previous
#include <cuda_runtime.h>
#include <math.h>

// GEBLNet fused kernel, round 9 = round-5 base + two surgical changes:
//  (1) diag+pair ordering of the unrolled element loop -> bp live regs 36 -> 8
//  (2) __launch_bounds__(160,5): 5 blocks/SM (occ 29% -> ~37%)
// Everything else identical to round 5 (best known: 170 us).

#define U    12
#define S1   13
#define S2   25
#define NB1  6
#define NB2  12
#define T1   (U*S1)      // 156
#define T2   (U*S2)      // 300
#define NT   160
#define NPTF 180

typedef unsigned long long u64;

__device__ float2 g_A1[NB1*T1], g_C1[T1];
__device__ float2 g_A2[NB2*T2], g_C2[T2];
__device__ float4 g_E1[NB1*T1];            // {er, -er, -ei, ei}  (signs precomputed)
__device__ float4 g_E2[NB2*T2];

__device__ __forceinline__ u64 pk(float lo, float hi) {
    u64 r; asm("mov.b64 %0,{%1,%2};" : "=l"(r) : "f"(lo), "f"(hi)); return r;
}
__device__ __forceinline__ void fma2(u64& d, u64 a, u64 b) {
    asm("fma.rn.f32x2 %0,%1,%2,%0;" : "+l"(d) : "l"(a), "l"(b));
}
__device__ __forceinline__ float2 up(u64 a) {
    float2 f; asm("mov.b64 {%0,%1},%2;" : "=f"(f.x), "=f"(f.y) : "l"(a)); return f;
}

__global__ void prep_w(const float* __restrict__ w1, const float* __restrict__ w2)
{
    int t = blockIdx.x * blockDim.x + threadIdx.x;
    if (t < T1) {
        const float* b = w1 + (size_t)t * S1 * 2;
        for (int w = 0; w < NB1; w++) {
            g_A1[w*T1 + t] = make_float2(b[2*w], b[2*w + 1]);
            float er = b[2*(NB1+w)], ei = b[2*(NB1+w) + 1];
            g_E1[w*T1 + t] = make_float4(er, -er, -ei, ei);
        }
        g_C1[t] = make_float2(b[2*(2*NB1)], b[2*(2*NB1) + 1]);
    }
    if (t < T2) {
        const float* b = w2 + (size_t)t * S2 * 2;
        for (int w = 0; w < NB2; w++) {
            g_A2[w*T2 + t] = make_float2(b[2*w], b[2*w + 1]);
            float er = b[2*(NB2+w)], ei = b[2*(NB2+w) + 1];
            g_E2[w*T2 + t] = make_float4(er, -er, -ei, ei);
        }
        g_C2[t] = make_float2(b[2*(2*NB2)], b[2*(2*NB2) + 1]);
    }
}

// C[u,v] = sum_w a_w*W[w] + sum_w e_w*W[w]^H + c*I, single accumulator:
//   acc[(i,k)] += {ar,ar}.b[(i,k)] + {ai,ai}.bs[(i,k)]
//              + {er,-er}.b[(k,i)] + {-ei,ei}.bs[(k,i)]
// Element order: diagonals {0,4,8} then symmetric pairs (1,3),(2,6),(5,7),
// so at most 2 bp values are live at a time.
template<int S, int NB, int TPT>
__device__ __forceinline__ void stage_c(const float2* __restrict__ gA,
                                        const float4* __restrict__ gE,
                                        const float2* __restrict__ gC,
                                        const ulonglong2* __restrict__ sWp,
                                        u64* __restrict__ sC, int tid)
{
    const int T = U * S;
    const int H = T / TPT;
    if (tid < H) {
        u64 acc[TPT][9];
#pragma unroll
        for (int t = 0; t < TPT; t++)
#pragma unroll
            for (int e = 0; e < 9; e++) acc[t][e] = 0ull;

#pragma unroll
        for (int w = 0; w < NB; ++w) {
            // per-task scalars first (front LDGs, small live set)
            u64 ar[TPT], ai[TPT], er[TPT], ei[TPT];
#pragma unroll
            for (int t = 0; t < TPT; t++) {
                int task = tid + t * H;
                float2 aw = __ldg(gA + w*T + task);
                float4 ef = __ldg(gE + w*T + task);
                ar[t] = pk(aw.x, aw.x); ai[t] = pk(aw.y, aw.y);
                er[t] = pk(ef.x, ef.y); ei[t] = pk(ef.z, ef.w);
            }
            const ulonglong2* wp = sWp + w*9;
            // diagonal elements (e == et): 1 bp live
#pragma unroll
            for (int d = 0; d < 3; d++) {
                const int e = d*4;                 // 0, 4, 8
                ulonglong2 bp = wp[e];
#pragma unroll
                for (int t = 0; t < TPT; t++) {
                    fma2(acc[t][e], ar[t], bp.x);
                    fma2(acc[t][e], ai[t], bp.y);
                    fma2(acc[t][e], er[t], bp.x);
                    fma2(acc[t][e], ei[t], bp.y);
                }
            }
            // symmetric pairs (e, et): 2 bp live
#pragma unroll
            for (int q = 0; q < 3; q++) {
                const int e  = (q == 0) ? 1 : (q == 1) ? 2 : 5;
                const int et = (q == 0) ? 3 : (q == 1) ? 6 : 7;
                ulonglong2 bpE = wp[e];
                ulonglong2 bpT = wp[et];
#pragma unroll
                for (int t = 0; t < TPT; t++) {
                    fma2(acc[t][e],  ar[t], bpE.x);
                    fma2(acc[t][e],  ai[t], bpE.y);
                    fma2(acc[t][e],  er[t], bpT.x);
                    fma2(acc[t][e],  ei[t], bpT.y);
                    fma2(acc[t][et], ar[t], bpT.x);
                    fma2(acc[t][et], ai[t], bpT.y);
                    fma2(acc[t][et], er[t], bpE.x);
                    fma2(acc[t][et], ei[t], bpE.y);
                }
            }
        }
        const u64 one2 = pk(1.0f, 1.0f);
#pragma unroll
        for (int t = 0; t < TPT; t++) {
            int task = tid + t * H;
            float2 cw = __ldg(gC + task);
            u64 cc = pk(cw.x, cw.y);
            fma2(acc[t][0], one2, cc);
            fma2(acc[t][4], one2, cc);
            fma2(acc[t][8], one2, cc);
#pragma unroll
            for (int e = 0; e < 9; e++) sC[e*T + task] = acc[t][e];
        }
    }
}

// wout[u](i,k) = sum_{v<NB} W[v](i,:)C[u,v](:,k)
//             + sum_{v<NB} W[v]^H(i,:)C[u,NB+v](:,k) + C[u,2NB](i,k)
template<int S, int NB>
__device__ __forceinline__ void stage_m(const ulonglong2* __restrict__ sWp,
                                        const u64* __restrict__ sC,
                                        u64* __restrict__ sM, int tid)
{
    const int T = U * S;
    if (tid < U * 9) {
        int u = tid / 9, e = tid % 9;
        int i = e / 3, k = e % 3;
        u64 a1 = 0ull, a2 = 0ull, a2c = 0ull;
        const u64* Cu = sC + u * S;
#pragma unroll
        for (int v = 0; v < NB; ++v) {
#pragma unroll
            for (int j = 0; j < 3; ++j) {
                float2 b = up(sWp[v*9 + i*3 + j].x);
                u64 c = Cu[(j*3 + k)*T + v];
                fma2(a1, pk(b.x, b.x), c);
                fma2(a2, pk(b.y, b.y), c);
            }
        }
#pragma unroll
        for (int v = 0; v < NB; ++v) {
#pragma unroll
            for (int j = 0; j < 3; ++j) {
                float2 b = up(sWp[v*9 + j*3 + i].x);
                u64 c = Cu[(j*3 + k)*T + NB + v];
                fma2(a1,  pk(b.x, b.x), c);
                fma2(a2c, pk(b.y, b.y), c);
            }
        }
        float2 p = up(a1), q = up(a2), qc = up(a2c);
        float2 ci = up(Cu[(i*3 + k)*T + 2*NB]);
        sM[u*9 + e] = pk(p.x - q.y + qc.y + ci.x,
                         p.y + q.x - qc.x + ci.y);
    }
}

__global__ __launch_bounds__(NT, 5)
void gebl_kernel(const float* __restrict__ x,
                 const float* __restrict__ dw,
                 const float* __restrict__ db,
                 float* __restrict__ out)
{
    __shared__ __align__(16) ulonglong2 sWp[NB2 * 9];   // 1728 B
    __shared__ u64   sC[9 * T2];                        // 21600 B
    __shared__ u64   sM[U * 9];                         // 864 B
    __shared__ float sTrRe[U], sTrIm[U], sAbs[U], sScale[U];
    __shared__ float sNormInv;

    const int tid   = threadIdx.x;
    const int point = blockIdx.x;
    const float2* xp = reinterpret_cast<const float2*>(x + (size_t)point * NPTF) + 4 * 9;

    // ---- Build base W1 ----
    if (tid < NB1 * 9) {
        float2 v = __ldg(xp + tid);
        sWp[tid] = make_ulonglong2(pk(v.x, v.y), pk(-v.y, v.x));
    }
    __syncthreads();

    // ---- Layer 1 ----
    stage_c<S1, NB1, 1>(g_A1, g_E1, g_C1, sWp, sC, tid);
    __syncthreads();
    stage_m<S1, NB1>(sWp, sC, sM, tid);
    __syncthreads();

    if (tid < U) {
        const u64* m = sM + tid*9;
        float2 t0 = up(m[0]), t4 = up(m[4]), t8 = up(m[8]);
        float trRe = t0.x + t4.x + t8.x;
        float trIm = t0.y + t4.y + t8.y;
        float t = fmaxf(trRe, 0.0f);
        sAbs[tid]   = t * sqrtf(trRe*trRe + trIm*trIm);
        sScale[tid] = t;
    }
    __syncthreads();
    if (tid == 0) {
        float s = 0.f;
#pragma unroll
        for (int u = 0; u < U; u++) s += sAbs[u];
        sNormInv = 1.0f / fmaxf(s * (1.0f / U), 0.001f);
    }
    __syncthreads();

    // ---- Build base W2 ----
    if (tid < U * 9) {
        int ch = tid / 9;
        float s = sScale[ch] * sNormInv;
        float2 m = up(sM[tid]);
        sWp[tid] = make_ulonglong2(pk(s*m.x, s*m.y), pk(-s*m.y, s*m.x));
    }
    __syncthreads();

    // ---- Layer 2 (2 tasks/thread) ----
    stage_c<S2, NB2, 2>(g_A2, g_E2, g_C2, sWp, sC, tid);
    __syncthreads();
    stage_m<S2, NB2>(sWp, sC, sM, tid);
    __syncthreads();

    // ---- Layer-2 scalars + head ----
    if (tid < U) {
        const u64* m = sM + tid*9;
        float2 t0 = up(m[0]), t4 = up(m[4]), t8 = up(m[8]);
        float trRe = t0.x + t4.x + t8.x;
        float trIm = t0.y + t4.y + t8.y;
        float t = fmaxf(trRe, 0.0f);
        sTrRe[tid]  = trRe;
        sTrIm[tid]  = trIm;
        sAbs[tid]   = t * sqrtf(trRe*trRe + trIm*trIm);
        sScale[tid] = t;
    }
    __syncthreads();
    if (tid == 0) {
        float s = 0.f;
#pragma unroll
        for (int u = 0; u < U; u++) s += sAbs[u];
        float inv_norm = 1.0f / fmaxf(s * (1.0f / U), 0.001f);
        float o = __ldg(&db[0]);
#pragma unroll
        for (int u = 0; u < U; u++) {
            float sc = sScale[u] * inv_norm * (1.0f / 3.0f);
            o = fmaf(sc * sTrRe[u], __ldg(&dw[2*u]),     o);
            o = fmaf(sc * sTrIm[u], __ldg(&dw[2*u + 1]), o);
        }
        out[point] = o;
    }
}

extern "C" void kernel_launch(void* const* d_in, const int* in_sizes, int n_in,
                              void* d_out, int out_size)
{
    const float* x  = (const float*)d_in[0];
    const float* w1 = (const float*)d_in[1];
    const float* w2 = (const float*)d_in[2];
    const float* dw = (const float*)d_in[3];
    const float* db = (const float*)d_in[4];
    float* out = (float*)d_out;

    int points = in_sizes[0] / NPTF;   // 8192

    prep_w<<<1, 320>>>(w1, w2);
    gebl_kernel<<<points, NT>>>(x, dw, db, out);
}